// round 4
// baseline (speedup 1.0000x reference)
#include <cuda_runtime.h>
#include <math.h>

#define BATCH 64
#define NTOK  4096
#define NS    8
#define SCALE 0.125f
#define EPSV  1e-8f
#define LN_EPS 1e-5f

__device__ float g_slots[BATCH][NS][64];
__device__ float g_Qk[BATCH][NS][64];
__device__ float g_T[BATCH][NS];
__device__ float g_C[BATCH][NS];
__device__ float g_Z[BATCH][NS][64];
__device__ float g_beta[BATCH][NS];
__device__ float g_Sa[BATCH][NS];

__global__ void k_init(const float* __restrict__ noise,
                       const float* __restrict__ smu,
                       const float* __restrict__ ssig)
{
    int b = blockIdx.x, t = threadIdx.x, c = t & 63;
    ((float*)g_slots[b])[t] = smu[c] + ssig[c] * noise[b * 512 + t];
}

// per batch: slots -> LN -> q -> Qk/T/C ; zero accumulators
__global__ void __launch_bounds__(256) k_prep(
    const float* __restrict__ Wq, const float* __restrict__ bq,
    const float* __restrict__ Wk, const float* __restrict__ bk,
    const float* __restrict__ ln_s_w, const float* __restrict__ ln_s_b,
    const float* __restrict__ ln_in_w, const float* __restrict__ ln_in_b)
{
    __shared__ float sn_s[NS][64];
    __shared__ float q_s[NS][64];
    __shared__ float W_s[64][65];
    __shared__ float bkq_s[NS], t_s[NS], c_s[NS];

    int b = blockIdx.x, t = threadIdx.x;
    if (t < 8) { bkq_s[t] = 0.f; t_s[t] = 0.f; c_s[t] = 0.f; }

    int wj = t >> 5, lane = t & 31;
    {
        float v0 = g_slots[b][wj][lane];
        float v1 = g_slots[b][wj][lane + 32];
        float s = v0 + v1, s2 = v0 * v0 + v1 * v1;
        #pragma unroll
        for (int k = 16; k >= 1; k >>= 1) {
            s  += __shfl_xor_sync(0xffffffffu, s,  k);
            s2 += __shfl_xor_sync(0xffffffffu, s2, k);
        }
        float mu = s * (1.f / 64.f);
        float rstd = rsqrtf(s2 * (1.f / 64.f) - mu * mu + LN_EPS);
        sn_s[wj][lane]      = (v0 - mu) * rstd * ln_s_w[lane]      + ln_s_b[lane];
        sn_s[wj][lane + 32] = (v1 - mu) * rstd * ln_s_w[lane + 32] + ln_s_b[lane + 32];
    }
    for (int i = t; i < 4096; i += 256) W_s[i >> 6][i & 63] = Wq[i];
    __syncthreads();

    #pragma unroll
    for (int k = 0; k < 2; k++) {
        int o = t + k * 256, j = o >> 6, a = o & 63;
        float acc = bq[a];
        #pragma unroll 16
        for (int c = 0; c < 64; c++) acc += sn_s[j][c] * W_s[a][c];
        q_s[j][a] = acc;
        atomicAdd(&bkq_s[j], bk[a] * acc);
    }
    __syncthreads();
    for (int i = t; i < 4096; i += 256) W_s[i >> 6][i & 63] = Wk[i];
    __syncthreads();

    #pragma unroll
    for (int k = 0; k < 2; k++) {
        int o = t + k * 256, j = o >> 6, c = o & 63;
        float acc = 0.f;
        #pragma unroll 16
        for (int a = 0; a < 64; a++) acc += W_s[a][c] * q_s[j][a];
        float Qkv = SCALE * ln_in_w[c] * acc;
        g_Qk[b][j][c] = Qkv;
        atomicAdd(&t_s[j], Qkv);
        atomicAdd(&c_s[j], SCALE * ln_in_b[c] * acc);
    }
    for (int i = t; i < 512; i += 256) ((float*)g_Z[b])[i] = 0.f;
    __syncthreads();
    if (t < 8) {
        g_T[b][t] = t_s[t];
        g_C[b][t] = c_s[t] + SCALE * bkq_s[t];
        g_beta[b][t] = 0.f;
        g_Sa[b][t]   = 0.f;
    }
}

// heavy pass: grid(16, BATCH), 128 threads
__global__ void __launch_bounds__(128) k_stream(
    const float* __restrict__ inputs, const int* __restrict__ mask)
{
    __shared__ __align__(16) float4 Qk4[NS][16];
    __shared__ float T_s[NS], C_s[NS];
    __shared__ __align__(16) float x_s[128 * 66];
    __shared__ __align__(16) float alphaT[NS][132];
    __shared__ float Zred[NS][64];
    __shared__ float Sa_red[NS], Be_red[NS];

    int b = blockIdx.y, chunk = blockIdx.x, t = threadIdx.x;
    int w = t >> 5, lane = t & 31;

    {
        const float* qg = &g_Qk[b][0][0];
        for (int i = t; i < 512; i += 128) ((float*)Qk4)[i] = qg[i];
        if (t < 8) { T_s[t] = g_T[b][t]; C_s[t] = g_C[b][t]; }
    }
    for (int i = t; i < 512; i += 128) ((float*)Zred)[i] = 0.f;
    if (t < 8) { Sa_red[t] = 0.f; Be_red[t] = 0.f; }
    __syncthreads();

    float sa_acc[8], be_acc[8], z0[8], z1[8];
    #pragma unroll
    for (int j = 0; j < 8; j++) { sa_acc[j] = 0.f; be_acc[j] = 0.f; z0[j] = 0.f; z1[j] = 0.f; }

    #pragma unroll 1
    for (int tile = 0; tile < 2; tile++) {
        int row = chunk * 256 + tile * 128 + t;
        const float4* xp = (const float4*)(inputs + ((size_t)b * NTOK + row) * 64);
        float4 v[16];
        #pragma unroll
        for (int i = 0; i < 16; i++) v[i] = xp[i];

        float s = 0.f, s2 = 0.f;
        #pragma unroll
        for (int i = 0; i < 16; i++) {
            s  += (v[i].x + v[i].y) + (v[i].z + v[i].w);
            s2 += v[i].x * v[i].x + v[i].y * v[i].y + v[i].z * v[i].z + v[i].w * v[i].w;
        }
        float mu = s * (1.f / 64.f);
        float rstd = rsqrtf(s2 * (1.f / 64.f) - mu * mu + LN_EPS);
        float mval = (mask[(size_t)b * NTOK + row] != 0) ? 1.f : 0.f;

        {
            float* xrow = &x_s[t * 66];
            #pragma unroll
            for (int i = 0; i < 16; i++) {
                ((float2*)xrow)[2 * i]     = make_float2(v[i].x, v[i].y);
                ((float2*)xrow)[2 * i + 1] = make_float2(v[i].z, v[i].w);
            }
        }

        float d[8];
        #pragma unroll
        for (int j = 0; j < 8; j++) {
            float a0 = 0.f, a1 = 0.f, a2 = 0.f, a3 = 0.f;
            #pragma unroll
            for (int i = 0; i < 16; i++) {
                float4 qk = Qk4[j][i];
                a0 += v[i].x * qk.x; a1 += v[i].y * qk.y;
                a2 += v[i].z * qk.z; a3 += v[i].w * qk.w;
            }
            d[j] = rstd * (((a0 + a1) + (a2 + a3)) - mu * T_s[j]) + C_s[j];
        }
        float mx = d[0];
        #pragma unroll
        for (int j = 1; j < 8; j++) mx = fmaxf(mx, d[j]);
        float e[8], se = 0.f;
        #pragma unroll
        for (int j = 0; j < 8; j++) { e[j] = __expf(d[j] - mx); se += e[j]; }
        float inv = __fdividef(1.f, se);
        #pragma unroll
        for (int j = 0; j < 8; j++) {
            float a  = (e[j] * inv + EPSV) * mval;
            float al = a * rstd;
            sa_acc[j] += a;
            be_acc[j] += al * mu;
            alphaT[j][t] = al;
        }
        __syncthreads();

        for (int r0 = w * 32; r0 < w * 32 + 32; r0 += 4) {
            float a0[8], a1[8], a2[8], a3[8];
            #pragma unroll
            for (int j = 0; j < 8; j++) {
                float4 av = *(const float4*)&alphaT[j][r0];
                a0[j] = av.x; a1[j] = av.y; a2[j] = av.z; a3[j] = av.w;
            }
            float2 x0 = *(const float2*)&x_s[(r0 + 0) * 66 + 2 * lane];
            float2 x1 = *(const float2*)&x_s[(r0 + 1) * 66 + 2 * lane];
            float2 x2 = *(const float2*)&x_s[(r0 + 2) * 66 + 2 * lane];
            float2 x3 = *(const float2*)&x_s[(r0 + 3) * 66 + 2 * lane];
            #pragma unroll
            for (int j = 0; j < 8; j++) {
                z0[j] += a0[j] * x0.x; z1[j] += a0[j] * x0.y;
                z0[j] += a1[j] * x1.x; z1[j] += a1[j] * x1.y;
                z0[j] += a2[j] * x2.x; z1[j] += a2[j] * x2.y;
                z0[j] += a3[j] * x3.x; z1[j] += a3[j] * x3.y;
            }
        }
        __syncthreads();
    }

    #pragma unroll
    for (int j = 0; j < 8; j++) {
        atomicAdd(&Zred[j][2 * lane],     z0[j]);
        atomicAdd(&Zred[j][2 * lane + 1], z1[j]);
        atomicAdd(&Sa_red[j], sa_acc[j]);
        atomicAdd(&Be_red[j], be_acc[j]);
    }
    __syncthreads();
    for (int i = t; i < 512; i += 128) atomicAdd(&((float*)g_Z[b])[i], ((float*)Zred)[i]);
    if (t < 8) {
        atomicAdd(&g_Sa[b][t],   Sa_red[t]);
        atomicAdd(&g_beta[b][t], Be_red[t]);
    }
}

// per batch: updates -> GRU -> MLP -> new slots (+ write out)
__global__ void __launch_bounds__(256) k_update(
    const float* __restrict__ Wv,  const float* __restrict__ bv,
    const float* __restrict__ W_ih, const float* __restrict__ b_ih,
    const float* __restrict__ W_hh, const float* __restrict__ b_hh,
    const float* __restrict__ W1,  const float* __restrict__ b1,
    const float* __restrict__ W2,  const float* __restrict__ b2,
    const float* __restrict__ ln_in_w, const float* __restrict__ ln_in_b,
    const float* __restrict__ ln_ff_w, const float* __restrict__ ln_ff_b,
    float* __restrict__ out, int last)
{
    __shared__ float Y_s[NS][64];
    __shared__ float sl_s[NS][64];
    __shared__ float upd_s[NS][64];
    __shared__ float gx_s[NS][192];
    __shared__ float gh_s[NS][192];
    __shared__ float sn_s[NS][64];
    __shared__ float ff_s[NS][64];
    __shared__ float h1_s[NS][128];
    __shared__ float Sa_s[NS], Be_s[NS];

    int b = blockIdx.x, t = threadIdx.x;
    if (t < 8) { Sa_s[t] = g_Sa[b][t]; Be_s[t] = g_beta[b][t]; }
    for (int i = t; i < 512; i += 256) ((float*)sl_s)[i] = ((const float*)g_slots[b])[i];
    __syncthreads();

    #pragma unroll
    for (int k = 0; k < 2; k++) {
        int o = t + k * 256, j = o >> 6, c = o & 63;
        Y_s[j][c] = ln_in_w[c] * (g_Z[b][j][c] - Be_s[j]) + ln_in_b[c] * Sa_s[j];
    }
    __syncthreads();

    #pragma unroll
    for (int k = 0; k < 2; k++) {
        int o = t + k * 256, j = o >> 6, dv = o & 63;
        float acc = 0.f;
        const float* wr = Wv + dv * 64;
        #pragma unroll 16
        for (int c = 0; c < 64; c++) acc += wr[c] * Y_s[j][c];
        upd_s[j][dv] = acc * __fdividef(1.f, Sa_s[j]) + bv[dv];
    }
    __syncthreads();

    for (int o = t; o < 1536; o += 256) {
        int j = o / 192, g = o % 192;
        float ax = b_ih[g], ah = b_hh[g];
        const float* wx = W_ih + g * 64;
        const float* wh = W_hh + g * 64;
        #pragma unroll 16
        for (int dd = 0; dd < 64; dd++) {
            ax += wx[dd] * upd_s[j][dd];
            ah += wh[dd] * sl_s[j][dd];
        }
        gx_s[j][g] = ax; gh_s[j][g] = ah;
    }
    __syncthreads();

    #pragma unroll
    for (int k = 0; k < 2; k++) {
        int o = t + k * 256, j = o >> 6, dd = o & 63;
        float r = 1.f / (1.f + __expf(-(gx_s[j][dd] + gh_s[j][dd])));
        float z = 1.f / (1.f + __expf(-(gx_s[j][64 + dd] + gh_s[j][64 + dd])));
        float nn = tanhf(gx_s[j][128 + dd] + r * gh_s[j][128 + dd]);
        sn_s[j][dd] = (1.f - z) * nn + z * sl_s[j][dd];
    }
    __syncthreads();

    {
        int wj = t >> 5, lane = t & 31;
        float v0 = sn_s[wj][lane], v1 = sn_s[wj][lane + 32];
        float s = v0 + v1, s2 = v0 * v0 + v1 * v1;
        #pragma unroll
        for (int k = 16; k >= 1; k >>= 1) {
            s  += __shfl_xor_sync(0xffffffffu, s,  k);
            s2 += __shfl_xor_sync(0xffffffffu, s2, k);
        }
        float mu = s * (1.f / 64.f);
        float rstd = rsqrtf(s2 * (1.f / 64.f) - mu * mu + LN_EPS);
        ff_s[wj][lane]      = (v0 - mu) * rstd * ln_ff_w[lane]      + ln_ff_b[lane];
        ff_s[wj][lane + 32] = (v1 - mu) * rstd * ln_ff_w[lane + 32] + ln_ff_b[lane + 32];
    }
    __syncthreads();

    for (int o = t; o < 1024; o += 256) {
        int j = o >> 7, ee = o & 127;
        float acc = b1[ee];
        const float* w1r = W1 + ee * 64;
        #pragma unroll 16
        for (int dd = 0; dd < 64; dd++) acc += w1r[dd] * ff_s[j][dd];
        h1_s[j][ee] = fmaxf(acc, 0.f);
    }
    __syncthreads();

    #pragma unroll
    for (int k = 0; k < 2; k++) {
        int o = t + k * 256, j = o >> 6, dd = o & 63;
        float acc = b2[dd];
        const float* w2r = W2 + dd * 128;
        #pragma unroll 16
        for (int e = 0; e < 128; e++) acc += w2r[e] * h1_s[j][e];
        float val = sn_s[j][dd] + acc;
        g_slots[b][j][dd] = val;
        if (last) out[(size_t)b * 512 + o] = val;
    }
}

extern "C" void kernel_launch(void* const* d_in, const int* in_sizes, int n_in,
                              void* d_out, int out_size)
{
    const float* inputs = (const float*)d_in[0];
    const int*   mask   = (const int*)  d_in[1];
    const float* noise  = (const float*)d_in[2];
    const float* smu    = (const float*)d_in[3];
    const float* ssig   = (const float*)d_in[4];
    const float* Wq = (const float*)d_in[5];  const float* bq = (const float*)d_in[6];
    const float* Wk = (const float*)d_in[7];  const float* bk = (const float*)d_in[8];
    const float* Wv = (const float*)d_in[9];  const float* bv = (const float*)d_in[10];
    const float* W_ih = (const float*)d_in[11]; const float* b_ih = (const float*)d_in[12];
    const float* W_hh = (const float*)d_in[13]; const float* b_hh = (const float*)d_in[14];
    const float* W1 = (const float*)d_in[15]; const float* b1 = (const float*)d_in[16];
    const float* W2 = (const float*)d_in[17]; const float* b2 = (const float*)d_in[18];
    const float* ln_in_w = (const float*)d_in[19]; const float* ln_in_b = (const float*)d_in[20];
    const float* ln_s_w  = (const float*)d_in[21]; const float* ln_s_b  = (const float*)d_in[22];
    const float* ln_ff_w = (const float*)d_in[23]; const float* ln_ff_b = (const float*)d_in[24];
    float* out = (float*)d_out;

    k_init<<<BATCH, 512>>>(noise, smu, ssig);
    for (int it = 0; it < 3; it++) {
        k_prep<<<BATCH, 256>>>(Wq, bq, Wk, bk, ln_s_w, ln_s_b, ln_in_w, ln_in_b);
        k_stream<<<dim3(16, BATCH), 128>>>(inputs, mask);
        k_update<<<BATCH, 256>>>(Wv, bv, W_ih, b_ih, W_hh, b_hh, W1, b1, W2, b2,
                                 ln_in_w, ln_in_b, ln_ff_w, ln_ff_b, out, it == 2);
    }
}

// round 8
// speedup vs baseline: 1.9549x; 1.9549x over previous
#include <cuda_runtime.h>
#include <math.h>

#define BATCH 64
#define NTOK  4096
#define NS    8
#define SCALE 0.125f
#define EPSV  1e-8f
#define LN_EPS 1e-5f

__device__ float g_slots[BATCH][NS][64];
__device__ float g_Qk[BATCH][NS][64];
__device__ float g_T[BATCH][NS];
__device__ float g_C[BATCH][NS];
__device__ float g_Z[BATCH][NS][64];
__device__ float g_beta[BATCH][NS];
__device__ float g_Sa[BATCH][NS];

__global__ void k_init(const float* __restrict__ noise,
                       const float* __restrict__ smu,
                       const float* __restrict__ ssig)
{
    int b = blockIdx.x, t = threadIdx.x, c = t & 63;
    ((float*)g_slots[b])[t] = smu[c] + ssig[c] * noise[b * 512 + t];
}

// per batch: slots -> LN -> q -> Qk/T/C ; zero accumulators
__global__ void __launch_bounds__(256) k_prep(
    const float* __restrict__ Wq, const float* __restrict__ bq,
    const float* __restrict__ Wk, const float* __restrict__ bk,
    const float* __restrict__ ln_s_w, const float* __restrict__ ln_s_b,
    const float* __restrict__ ln_in_w, const float* __restrict__ ln_in_b)
{
    __shared__ float sn_s[NS][64];
    __shared__ float q_s[NS][64];
    __shared__ float W_s[64][65];
    __shared__ float bkq_s[NS], t_s[NS], c_s[NS];

    int b = blockIdx.x, t = threadIdx.x;
    if (t < 8) { bkq_s[t] = 0.f; t_s[t] = 0.f; c_s[t] = 0.f; }

    int wj = t >> 5, lane = t & 31;
    {
        float v0 = g_slots[b][wj][lane];
        float v1 = g_slots[b][wj][lane + 32];
        float s = v0 + v1, s2 = v0 * v0 + v1 * v1;
        #pragma unroll
        for (int k = 16; k >= 1; k >>= 1) {
            s  += __shfl_xor_sync(0xffffffffu, s,  k);
            s2 += __shfl_xor_sync(0xffffffffu, s2, k);
        }
        float mu = s * (1.f / 64.f);
        float rstd = rsqrtf(s2 * (1.f / 64.f) - mu * mu + LN_EPS);
        sn_s[wj][lane]      = (v0 - mu) * rstd * ln_s_w[lane]      + ln_s_b[lane];
        sn_s[wj][lane + 32] = (v1 - mu) * rstd * ln_s_w[lane + 32] + ln_s_b[lane + 32];
    }
    for (int i = t; i < 4096; i += 256) W_s[i >> 6][i & 63] = Wq[i];
    __syncthreads();

    #pragma unroll
    for (int k = 0; k < 2; k++) {
        int o = t + k * 256, j = o >> 6, a = o & 63;
        float acc = bq[a];
        #pragma unroll 16
        for (int c = 0; c < 64; c++) acc += sn_s[j][c] * W_s[a][c];
        q_s[j][a] = acc;
        atomicAdd(&bkq_s[j], bk[a] * acc);
    }
    __syncthreads();
    for (int i = t; i < 4096; i += 256) W_s[i >> 6][i & 63] = Wk[i];
    __syncthreads();

    #pragma unroll
    for (int k = 0; k < 2; k++) {
        int o = t + k * 256, j = o >> 6, c = o & 63;
        float acc = 0.f;
        #pragma unroll 16
        for (int a = 0; a < 64; a++) acc += W_s[a][c] * q_s[j][a];
        float Qkv = SCALE * ln_in_w[c] * acc;
        g_Qk[b][j][c] = Qkv;
        atomicAdd(&t_s[j], Qkv);
        atomicAdd(&c_s[j], SCALE * ln_in_b[c] * acc);
    }
    for (int i = t; i < 512; i += 256) ((float*)g_Z[b])[i] = 0.f;
    __syncthreads();
    if (t < 8) {
        g_T[b][t] = t_s[t];
        g_C[b][t] = c_s[t] + SCALE * bkq_s[t];
        g_beta[b][t] = 0.f;
        g_Sa[b][t]   = 0.f;
    }
}

// heavy pass: grid(16, BATCH), 128 threads
__global__ void __launch_bounds__(128) k_stream(
    const float* __restrict__ inputs, const int* __restrict__ mask)
{
    __shared__ __align__(16) float4 Qk4[NS][16];
    __shared__ float T_s[NS], C_s[NS];
    __shared__ __align__(16) float x_s[128 * 66];
    __shared__ __align__(16) float alphaT[NS][132];
    __shared__ float Zred[NS][64];
    __shared__ float Sa_red[NS], Be_red[NS];

    int b = blockIdx.y, chunk = blockIdx.x, t = threadIdx.x;
    int w = t >> 5, lane = t & 31;

    {
        const float* qg = &g_Qk[b][0][0];
        for (int i = t; i < 512; i += 128) ((float*)Qk4)[i] = qg[i];
        if (t < 8) { T_s[t] = g_T[b][t]; C_s[t] = g_C[b][t]; }
    }
    for (int i = t; i < 512; i += 128) ((float*)Zred)[i] = 0.f;
    if (t < 8) { Sa_red[t] = 0.f; Be_red[t] = 0.f; }
    __syncthreads();

    float sa_acc[8], be_acc[8], z0[8], z1[8];
    #pragma unroll
    for (int j = 0; j < 8; j++) { sa_acc[j] = 0.f; be_acc[j] = 0.f; z0[j] = 0.f; z1[j] = 0.f; }

    #pragma unroll 1
    for (int tile = 0; tile < 2; tile++) {
        int row = chunk * 256 + tile * 128 + t;
        const float4* xp = (const float4*)(inputs + ((size_t)b * NTOK + row) * 64);
        float4 v[16];
        #pragma unroll
        for (int i = 0; i < 16; i++) v[i] = xp[i];

        float s = 0.f, s2 = 0.f;
        #pragma unroll
        for (int i = 0; i < 16; i++) {
            s  += (v[i].x + v[i].y) + (v[i].z + v[i].w);
            s2 += v[i].x * v[i].x + v[i].y * v[i].y + v[i].z * v[i].z + v[i].w * v[i].w;
        }
        float mu = s * (1.f / 64.f);
        float rstd = rsqrtf(s2 * (1.f / 64.f) - mu * mu + LN_EPS);
        float mval = (mask[(size_t)b * NTOK + row] != 0) ? 1.f : 0.f;

        {
            float* xrow = &x_s[t * 66];
            #pragma unroll
            for (int i = 0; i < 16; i++) {
                ((float2*)xrow)[2 * i]     = make_float2(v[i].x, v[i].y);
                ((float2*)xrow)[2 * i + 1] = make_float2(v[i].z, v[i].w);
            }
        }

        float d[8];
        #pragma unroll
        for (int j = 0; j < 8; j++) {
            float a0 = 0.f, a1 = 0.f, a2 = 0.f, a3 = 0.f;
            #pragma unroll
            for (int i = 0; i < 16; i++) {
                float4 qk = Qk4[j][i];
                a0 += v[i].x * qk.x; a1 += v[i].y * qk.y;
                a2 += v[i].z * qk.z; a3 += v[i].w * qk.w;
            }
            d[j] = rstd * (((a0 + a1) + (a2 + a3)) - mu * T_s[j]) + C_s[j];
        }
        float mx = d[0];
        #pragma unroll
        for (int j = 1; j < 8; j++) mx = fmaxf(mx, d[j]);
        float e[8], se = 0.f;
        #pragma unroll
        for (int j = 0; j < 8; j++) { e[j] = __expf(d[j] - mx); se += e[j]; }
        float inv = __fdividef(1.f, se);
        #pragma unroll
        for (int j = 0; j < 8; j++) {
            float a  = (e[j] * inv + EPSV) * mval;
            float al = a * rstd;
            sa_acc[j] += a;
            be_acc[j] += al * mu;
            alphaT[j][t] = al;
        }
        __syncthreads();

        for (int r0 = w * 32; r0 < w * 32 + 32; r0 += 4) {
            float a0[8], a1[8], a2[8], a3[8];
            #pragma unroll
            for (int j = 0; j < 8; j++) {
                float4 av = *(const float4*)&alphaT[j][r0];
                a0[j] = av.x; a1[j] = av.y; a2[j] = av.z; a3[j] = av.w;
            }
            float2 x0 = *(const float2*)&x_s[(r0 + 0) * 66 + 2 * lane];
            float2 x1 = *(const float2*)&x_s[(r0 + 1) * 66 + 2 * lane];
            float2 x2 = *(const float2*)&x_s[(r0 + 2) * 66 + 2 * lane];
            float2 x3 = *(const float2*)&x_s[(r0 + 3) * 66 + 2 * lane];
            #pragma unroll
            for (int j = 0; j < 8; j++) {
                z0[j] += a0[j] * x0.x; z1[j] += a0[j] * x0.y;
                z0[j] += a1[j] * x1.x; z1[j] += a1[j] * x1.y;
                z0[j] += a2[j] * x2.x; z1[j] += a2[j] * x2.y;
                z0[j] += a3[j] * x3.x; z1[j] += a3[j] * x3.y;
            }
        }
        __syncthreads();
    }

    #pragma unroll
    for (int j = 0; j < 8; j++) {
        atomicAdd(&Zred[j][2 * lane],     z0[j]);
        atomicAdd(&Zred[j][2 * lane + 1], z1[j]);
        atomicAdd(&Sa_red[j], sa_acc[j]);
        atomicAdd(&Be_red[j], be_acc[j]);
    }
    __syncthreads();
    for (int i = t; i < 512; i += 128) atomicAdd(&((float*)g_Z[b])[i], ((float*)Zred)[i]);
    if (t < 8) {
        atomicAdd(&g_Sa[b][t],   Sa_red[t]);
        atomicAdd(&g_beta[b][t], Be_red[t]);
    }
}

// per batch: updates -> GRU -> MLP -> new slots (+ write out)
// All weight matrices staged into dynamic smem with COALESCED loads
// (old version read them strided from global: 32 wavefronts/LDG -> 197us)
__global__ void __launch_bounds__(256) k_update(
    const float* __restrict__ Wv,  const float* __restrict__ bv,
    const float* __restrict__ W_ih, const float* __restrict__ b_ih,
    const float* __restrict__ W_hh, const float* __restrict__ b_hh,
    const float* __restrict__ W1,  const float* __restrict__ b1,
    const float* __restrict__ W2,  const float* __restrict__ b2,
    const float* __restrict__ ln_in_w, const float* __restrict__ ln_in_b,
    const float* __restrict__ ln_ff_w, const float* __restrict__ ln_ff_b,
    float* __restrict__ out, int last)
{
    extern __shared__ float Wsm[];          // 192*65 floats = 49920 B
    __shared__ float Y_s[NS][64];
    __shared__ float sl_s[NS][64];
    __shared__ float upd_s[NS][64];
    __shared__ float gx_s[NS][192];
    __shared__ float gh_s[NS][192];
    __shared__ float sn_s[NS][64];
    __shared__ float ff_s[NS][64];
    __shared__ float h1_s[NS][128];
    __shared__ float Sa_s[NS], Be_s[NS];

    int b = blockIdx.x, t = threadIdx.x;
    if (t < 8) { Sa_s[t] = g_Sa[b][t]; Be_s[t] = g_beta[b][t]; }
    for (int i = t; i < 512; i += 256) ((float*)sl_s)[i] = ((const float*)g_slots[b])[i];
    // stage Wv [64][64] -> stride 65 (coalesced global read)
    for (int i = t; i < 4096; i += 256) Wsm[(i >> 6) * 65 + (i & 63)] = Wv[i];
    __syncthreads();

    #pragma unroll
    for (int k = 0; k < 2; k++) {
        int o = t + k * 256, j = o >> 6, c = o & 63;
        Y_s[j][c] = ln_in_w[c] * (g_Z[b][j][c] - Be_s[j]) + ln_in_b[c] * Sa_s[j];
    }
    __syncthreads();

    // updates = Wv @ Y / Sa + bv
    #pragma unroll
    for (int k = 0; k < 2; k++) {
        int o = t + k * 256, j = o >> 6, dv = o & 63;
        float acc = 0.f;
        const float* wr = &Wsm[dv * 65];
        #pragma unroll 16
        for (int c = 0; c < 64; c++) acc += wr[c] * Y_s[j][c];
        upd_s[j][dv] = acc * __fdividef(1.f, Sa_s[j]) + bv[dv];
    }
    __syncthreads();

    // stage W_ih [192][64] -> gx
    for (int i = t; i < 12288; i += 256) Wsm[(i >> 6) * 65 + (i & 63)] = W_ih[i];
    __syncthreads();
    for (int o = t; o < 1536; o += 256) {
        int j = o / 192, g = o % 192;
        float ax = b_ih[g];
        const float* wx = &Wsm[g * 65];
        #pragma unroll 16
        for (int dd = 0; dd < 64; dd++) ax += wx[dd] * upd_s[j][dd];
        gx_s[j][g] = ax;
    }
    __syncthreads();

    // stage W_hh [192][64] -> gh
    for (int i = t; i < 12288; i += 256) Wsm[(i >> 6) * 65 + (i & 63)] = W_hh[i];
    __syncthreads();
    for (int o = t; o < 1536; o += 256) {
        int j = o / 192, g = o % 192;
        float ah = b_hh[g];
        const float* wh = &Wsm[g * 65];
        #pragma unroll 16
        for (int dd = 0; dd < 64; dd++) ah += wh[dd] * sl_s[j][dd];
        gh_s[j][g] = ah;
    }
    __syncthreads();

    #pragma unroll
    for (int k = 0; k < 2; k++) {
        int o = t + k * 256, j = o >> 6, dd = o & 63;
        float r = 1.f / (1.f + __expf(-(gx_s[j][dd] + gh_s[j][dd])));
        float z = 1.f / (1.f + __expf(-(gx_s[j][64 + dd] + gh_s[j][64 + dd])));
        float nn = tanhf(gx_s[j][128 + dd] + r * gh_s[j][128 + dd]);
        sn_s[j][dd] = (1.f - z) * nn + z * sl_s[j][dd];
    }
    __syncthreads();

    // LN(ff): warp per slot
    {
        int wj = t >> 5, lane = t & 31;
        float v0 = sn_s[wj][lane], v1 = sn_s[wj][lane + 32];
        float s = v0 + v1, s2 = v0 * v0 + v1 * v1;
        #pragma unroll
        for (int k = 16; k >= 1; k >>= 1) {
            s  += __shfl_xor_sync(0xffffffffu, s,  k);
            s2 += __shfl_xor_sync(0xffffffffu, s2, k);
        }
        float mu = s * (1.f / 64.f);
        float rstd = rsqrtf(s2 * (1.f / 64.f) - mu * mu + LN_EPS);
        ff_s[wj][lane]      = (v0 - mu) * rstd * ln_ff_w[lane]      + ln_ff_b[lane];
        ff_s[wj][lane + 32] = (v1 - mu) * rstd * ln_ff_w[lane + 32] + ln_ff_b[lane + 32];
    }
    // stage W1 [128][64]
    for (int i = t; i < 8192; i += 256) Wsm[(i >> 6) * 65 + (i & 63)] = W1[i];
    __syncthreads();

    for (int o = t; o < 1024; o += 256) {
        int j = o >> 7, ee = o & 127;
        float acc = b1[ee];
        const float* w1r = &Wsm[ee * 65];
        #pragma unroll 16
        for (int dd = 0; dd < 64; dd++) acc += w1r[dd] * ff_s[j][dd];
        h1_s[j][ee] = fmaxf(acc, 0.f);
    }
    __syncthreads();

    // stage W2 [64][128] -> stride 129
    for (int i = t; i < 8192; i += 256) Wsm[(i >> 7) * 129 + (i & 127)] = W2[i];
    __syncthreads();

    #pragma unroll
    for (int k = 0; k < 2; k++) {
        int o = t + k * 256, j = o >> 6, dd = o & 63;
        float acc = b2[dd];
        const float* w2r = &Wsm[dd * 129];
        #pragma unroll 16
        for (int e = 0; e < 128; e++) acc += w2r[e] * h1_s[j][e];
        float val = sn_s[j][dd] + acc;
        g_slots[b][j][dd] = val;
        if (last) out[(size_t)b * 512 + o] = val;
    }
}

extern "C" void kernel_launch(void* const* d_in, const int* in_sizes, int n_in,
                              void* d_out, int out_size)
{
    const float* inputs = (const float*)d_in[0];
    const int*   mask   = (const int*)  d_in[1];
    const float* noise  = (const float*)d_in[2];
    const float* smu    = (const float*)d_in[3];
    const float* ssig   = (const float*)d_in[4];
    const float* Wq = (const float*)d_in[5];  const float* bq = (const float*)d_in[6];
    const float* Wk = (const float*)d_in[7];  const float* bk = (const float*)d_in[8];
    const float* Wv = (const float*)d_in[9];  const float* bv = (const float*)d_in[10];
    const float* W_ih = (const float*)d_in[11]; const float* b_ih = (const float*)d_in[12];
    const float* W_hh = (const float*)d_in[13]; const float* b_hh = (const float*)d_in[14];
    const float* W1 = (const float*)d_in[15]; const float* b1 = (const float*)d_in[16];
    const float* W2 = (const float*)d_in[17]; const float* b2 = (const float*)d_in[18];
    const float* ln_in_w = (const float*)d_in[19]; const float* ln_in_b = (const float*)d_in[20];
    const float* ln_s_w  = (const float*)d_in[21]; const float* ln_s_b  = (const float*)d_in[22];
    const float* ln_ff_w = (const float*)d_in[23]; const float* ln_ff_b = (const float*)d_in[24];
    float* out = (float*)d_out;

    static int smem_set = 0;
    if (!smem_set) {
        cudaFuncSetAttribute(k_update, cudaFuncAttributeMaxDynamicSharedMemorySize,
                             192 * 65 * (int)sizeof(float));
        smem_set = 1;
    }
    const int dyn = 192 * 65 * (int)sizeof(float);

    k_init<<<BATCH, 512>>>(noise, smu, ssig);
    for (int it = 0; it < 3; it++) {
        k_prep<<<BATCH, 256>>>(Wq, bq, Wk, bk, ln_s_w, ln_s_b, ln_in_w, ln_in_b);
        k_stream<<<dim3(16, BATCH), 128>>>(inputs, mask);
        k_update<<<BATCH, 256, dyn>>>(Wv, bv, W_ih, b_ih, W_hh, b_hh, W1, b1, W2, b2,
                                      ln_in_w, ln_in_b, ln_ff_w, ln_ff_b, out, it == 2);
    }
}